// round 4
// baseline (speedup 1.0000x reference)
#include <cuda_runtime.h>
#include <stdint.h>

#define NN   20000
#define RR   32
#define EMBD 16
#define HID  128
#define NE   600000
#define NSEG (NN*RR)

#define EPB1 1024
#define EPB2 512
#define GRID1 672
#define GRID2 1280

// ---------------- device scratch (no runtime allocation allowed) ----------------
__device__ int      g_is64;
__device__ unsigned g_cnt_seg[NSEG];     // per-(dst,rel) edge counts
__device__ int      g_rel_cnt[RR];
__device__ int      g_rel_ptr[RR + 1];
__device__ int      g_rel_cur[RR];
__device__ int      g_srcA[NE];
__device__ int      g_dstA[NE];
__device__ int      g_relA[NE];
__device__ unsigned g_epack[NE];         // rel-sorted: src | dst<<16
__device__ float    g_einv[NE];          // rel-sorted: 1/count(dst,rel)
__device__ float    g_h1[NN * HID];      // hidden activations

__device__ __forceinline__ void red_add_v4(float* p, float a, float b, float c, float d) {
    asm volatile("red.global.add.v4.f32 [%0], {%1,%2,%3,%4};"
                 :: "l"(p), "f"(a), "f"(b), "f"(c), "f"(d) : "memory");
}

// packed f32x2 FMA: d = a*b + d  (elementwise on the two packed floats)
__device__ __forceinline__ void fma2(unsigned long long& d,
                                     unsigned long long a, unsigned long long b) {
    asm("fma.rn.f32x2 %0, %1, %2, %0;" : "+l"(d) : "l"(a), "l"(b));
}
__device__ __forceinline__ float unpk_sum(unsigned long long v) {
    float lo, hi;
    asm("mov.b64 {%0,%1}, %2;" : "=f"(lo), "=f"(hi) : "l"(v));
    return lo + hi;
}

// ---------------- dtype sniff: int64 vs int32 edge indices ----------------
__global__ void k_sniff(const int* ei) {
    __shared__ int ok;
    if (threadIdx.x == 0) ok = 1;
    __syncthreads();
    int hi = ei[2 * threadIdx.x + 1];
    if (hi != 0) atomicExch(&ok, 0);
    __syncthreads();
    if (threadIdx.x == 0) g_is64 = ok;
}

__global__ void k_zero() {
    int i = blockIdx.x * blockDim.x + threadIdx.x;
    if (i < NSEG) g_cnt_seg[i] = 0u;
    if (i < RR)   g_rel_cnt[i] = 0;
}

__global__ void k_decode(const void* ei, const void* et) {
    int e = blockIdx.x * blockDim.x + threadIdx.x;
    if (e >= NE) return;
    if (g_is64) {
        const long long* a = (const long long*)ei;
        const long long* b = (const long long*)et;
        g_srcA[e] = (int)a[e];
        g_dstA[e] = (int)a[NE + e];
        g_relA[e] = (int)b[e];
    } else {
        const int* a = (const int*)ei;
        const int* b = (const int*)et;
        g_srcA[e] = a[e];
        g_dstA[e] = a[NE + e];
        g_relA[e] = b[e];
    }
}

__global__ void k_count() {
    __shared__ int sh[RR];
    int t = threadIdx.x;
    if (t < RR) sh[t] = 0;
    __syncthreads();
    int e = blockIdx.x * blockDim.x + t;
    if (e < NE) {
        int r = g_relA[e], d = g_dstA[e];
        atomicAdd(&g_cnt_seg[d * RR + r], 1u);
        atomicAdd(&sh[r], 1);
    }
    __syncthreads();
    if (t < RR && sh[t]) atomicAdd(&g_rel_cnt[t], sh[t]);
}

__global__ void k_scan() {
    int acc = 0;
    for (int r = 0; r < RR; r++) {
        g_rel_ptr[r] = acc;
        g_rel_cur[r] = acc;
        acc += g_rel_cnt[r];
    }
    g_rel_ptr[RR] = acc;
}

__global__ void k_scatter() {
    int e = blockIdx.x * blockDim.x + threadIdx.x;
    if (e >= NE) return;
    int r = g_relA[e], s = g_srcA[e], d = g_dstA[e];
    int pos = atomicAdd(&g_rel_cur[r], 1);
    g_epack[pos] = (unsigned)s | ((unsigned)d << 16);
    g_einv[pos]  = 1.0f / (float)g_cnt_seg[d * RR + r];
}

__global__ void k_init(const float* __restrict__ b1, const float* __restrict__ b2,
                       float* __restrict__ out) {
    int i = blockIdx.x * blockDim.x + threadIdx.x;
    if (i >= NN * HID) return;
    int h = i & (HID - 1);
    g_h1[i] = b1[h];
    out[i]  = b2[h];
}

__global__ void k_relu() {
    int i = blockIdx.x * blockDim.x + threadIdx.x;
    if (i < NN * HID) g_h1[i] = fmaxf(g_h1[i], 0.0f);
}

// ---------------- fused gather / tiny-GEMM / scatter-add per relation ----------------
// Inner product runs on packed fma.rn.f32x2 (FFMA2): the two packed halves carry
// the even-f / odd-f partial sums. Weights are transposed once per block into a
// layout where each lane's 4 columns x 2 f-parities come from two conflict-free
// LDS.128s.
template <int F, int EPB>
__global__ void __launch_bounds__(256)
k_layer(const float* __restrict__ Xext, float* __restrict__ Oext,
        const float* __restrict__ W, const float* __restrict__ Wroot, int layer) {
    extern __shared__ float sm[];
    float* Ws = sm;               // F * HID transposed weights for this relation
    float* hb = sm + F * HID;     // 8 warps * 8 edges * F staging (edge-major)

    const float* X   = (layer == 1) ? Xext : g_h1;
    float*       OUT = (layer == 1) ? g_h1 : Oext;

    const int tid  = threadIdx.x;
    const int lane = tid & 31;
    const int warp = tid >> 5;
    const int lane4 = lane * 4;

    // map block -> (relation, chunk)
    int bid = blockIdx.x, acc = 0, rel = -1, chunk = 0, cnt = 0;
    #pragma unroll 1
    for (int r = 0; r <= RR; r++) {
        int c  = (r < RR) ? g_rel_cnt[r] : NN;
        int nb = (c + EPB - 1) / EPB;
        if (bid < acc + nb) { rel = r; chunk = bid - acc; cnt = c; break; }
        acc += nb;
    }
    if (rel < 0) return;

    const float* Wp = (rel < RR) ? (W + (size_t)rel * F * HID) : Wroot;
    const int base   = (rel < RR) ? g_rel_ptr[rel] : 0;
    const int cstart = chunk * EPB;

    // stage weights into shared memory, transposed for packed-FMA access
    //   off(f,c) = (f>>1)*256 + ((c>>1)&1)*128 + (c>>2)*4 + (c&1)*2 + (f&1)
    for (int i = tid * 4; i < F * HID; i += 256 * 4) {
        float4 v = *(const float4*)&Wp[i];
        int f = i / HID, c0 = i & (HID - 1);
        int bse = (f >> 1) * 256 + (c0 >> 2) * 4 + (f & 1);
        Ws[bse + 0]   = v.x;   // c0   (half 0, sub 0)
        Ws[bse + 2]   = v.y;   // c0+1 (half 0, sub 1)
        Ws[bse + 128] = v.z;   // c0+2 (half 1, sub 0)
        Ws[bse + 130] = v.w;   // c0+3 (half 1, sub 1)
    }
    __syncthreads();

    float* hbw = hb + warp * (8 * F);
    const int ngroups = EPB / 8;

    for (int g = warp; g < ngroups; g += 8) {
        int gbase = cstart + g * 8;
        if (gbase >= cnt) break;

        // per-edge metadata, loaded by lanes 0..7 then broadcast
        int ms = 0, md = 0; float mi = 0.0f;
        if (lane < 8) {
            int gl = gbase + lane;
            if (gl < cnt) {
                if (rel < RR) {
                    unsigned pk = g_epack[base + gl];
                    ms = (int)(pk & 0xFFFFu);
                    md = (int)(pk >> 16);
                    mi = g_einv[base + gl];
                } else {
                    ms = gl; md = gl; mi = 1.0f;   // root pseudo-edge
                }
            }
        }
        int srcs[8], dsts[8]; float invs[8];
        #pragma unroll
        for (int e = 0; e < 8; e++) {
            srcs[e] = __shfl_sync(0xffffffffu, ms, e);
            dsts[e] = __shfl_sync(0xffffffffu, md, e);
            invs[e] = __shfl_sync(0xffffffffu, mi, e);
        }

        __syncwarp();
        // gather 8 source feature rows into shared staging (edge-major)
        if constexpr (F == 16) {
            if (lane < 16) {
                #pragma unroll
                for (int e = 0; e < 8; e++)
                    hbw[e * F + lane] = X[(size_t)srcs[e] * F + lane];
            }
        } else {
            #pragma unroll
            for (int e = 0; e < 8; e++)
                *(float4*)&hbw[e * F + lane4] = *(const float4*)&X[(size_t)srcs[e] * F + lane4];
        }
        __syncwarp();

        // 8-edge x 4-col tile; each acc packs (even-f, odd-f) partial sums
        unsigned long long a0[8], a1[8], a2[8], a3[8];
        #pragma unroll
        for (int e = 0; e < 8; e++) { a0[e] = 0ull; a1[e] = 0ull; a2[e] = 0ull; a3[e] = 0ull; }

        #pragma unroll 2
        for (int fp = 0; fp < F / 2; fp++) {
            const float* wrow = &Ws[fp * 256];
            // two conflict-free 16B loads: cols (4L,4L+1) then (4L+2,4L+3), each as (f,f+1) pairs
            ulonglong2 wA = *(const ulonglong2*)&wrow[lane4];          // c=4L, c=4L+1
            ulonglong2 wB = *(const ulonglong2*)&wrow[128 + lane4];    // c=4L+2, c=4L+3
            #pragma unroll
            for (int e = 0; e < 8; e++) {
                unsigned long long hv2 = *(const unsigned long long*)&hbw[e * F + fp * 2];
                fma2(a0[e], hv2, wA.x);
                fma2(a1[e], hv2, wA.y);
                fma2(a2[e], hv2, wB.x);
                fma2(a3[e], hv2, wB.y);
            }
        }

        // scaled vector scatter-add
        #pragma unroll
        for (int e = 0; e < 8; e++) {
            float iv = invs[e];
            if (iv > 0.0f) {
                red_add_v4(OUT + (size_t)dsts[e] * HID + lane4,
                           unpk_sum(a0[e]) * iv, unpk_sum(a1[e]) * iv,
                           unpk_sum(a2[e]) * iv, unpk_sum(a3[e]) * iv);
            }
        }
        __syncwarp();
    }
}

// ---------------- launch ----------------
extern "C" void kernel_launch(void* const* d_in, const int* in_sizes, int n_in,
                              void* d_out, int out_size) {
    const void*  ei = d_in[0];
    const void*  et = d_in[1];
    const float* x  = (const float*)d_in[2];
    const float* W1 = (const float*)d_in[3];
    const float* r1 = (const float*)d_in[4];
    const float* b1 = (const float*)d_in[5];
    const float* W2 = (const float*)d_in[6];
    const float* r2 = (const float*)d_in[7];
    const float* b2 = (const float*)d_in[8];
    float* out = (float*)d_out;

    const int SM1 = (EMBD * HID + 8 * 8 * EMBD) * 4;   // 12 KB
    const int SM2 = (HID * HID + 8 * 8 * HID) * 4;     // 96 KB

    static bool attr_done = false;
    if (!attr_done) {
        cudaFuncSetAttribute((const void*)k_layer<HID, EPB2>,
                             cudaFuncAttributeMaxDynamicSharedMemorySize, SM2);
        attr_done = true;
    }

    k_sniff  <<<1, 256>>>((const int*)ei);
    k_zero   <<<(NSEG + 255) / 256, 256>>>();
    k_decode <<<(NE + 255) / 256, 256>>>(ei, et);
    k_count  <<<(NE + 255) / 256, 256>>>();
    k_scan   <<<1, 1>>>();
    k_scatter<<<(NE + 255) / 256, 256>>>();
    k_init   <<<(NN * HID + 255) / 256, 256>>>(b1, b2, out);

    // layer 1: EMB=16 -> HID, writes g_h1 (pre-initialized with b1)
    k_layer<EMBD, EPB1><<<GRID1, 256, SM1>>>(x, out, W1, r1, 1);
    k_relu   <<<(NN * HID + 255) / 256, 256>>>();
    // layer 2: HID -> HID, reads g_h1, writes out (pre-initialized with b2)
    k_layer<HID, EPB2><<<GRID2, 256, SM2>>>(x, out, W2, r2, 2);
}

// round 8
// speedup vs baseline: 1.0708x; 1.0708x over previous
#include <cuda_runtime.h>
#include <cuda_bf16.h>
#include <stdint.h>

#define NN   20000
#define RR   32
#define EMBD 16
#define HID  128
#define NE   600000
#define NSEG (NN*RR)

#define EPB1 1024
#define GRID1 672
#define GRID_T 5200           // >= sum ceil(cnt_r/128) + ceil(NN/128)

// ---------------- device scratch ----------------
__device__ int      g_is64;
__device__ unsigned g_cnt_seg[NSEG];
__device__ int      g_rel_cnt[RR];
__device__ int      g_rel_ptr[RR + 1];
__device__ int      g_rel_cur[RR];
__device__ int      g_srcA[NE];
__device__ int      g_dstA[NE];
__device__ int      g_relA[NE];
__device__ unsigned g_epack[NE];
__device__ float    g_einv[NE];
__device__ float    g_h1[NN * HID];
__device__ __nv_bfloat16 g_h1hi[NN * HID];
__device__ __nv_bfloat16 g_h1lo[NN * HID];
__device__ __nv_bfloat16 g_w2hi[(RR + 1) * HID * HID];  // [r][n][k] (r=32 -> root2)
__device__ __nv_bfloat16 g_w2lo[(RR + 1) * HID * HID];

__device__ __forceinline__ void red_add_v4(float* p, float a, float b, float c, float d) {
    asm volatile("red.global.add.v4.f32 [%0], {%1,%2,%3,%4};"
                 :: "l"(p), "f"(a), "f"(b), "f"(c), "f"(d) : "memory");
}
__device__ __forceinline__ void red_add_v2(float* p, float a, float b) {
    asm volatile("red.global.add.v2.f32 [%0], {%1,%2};"
                 :: "l"(p), "f"(a), "f"(b) : "memory");
}

__device__ __forceinline__ uint32_t smem_u32(const void* p) {
    uint32_t a;
    asm("{ .reg .u64 t; cvta.to.shared.u64 t, %1; cvt.u32.u64 %0, t; }" : "=r"(a) : "l"(p));
    return a;
}

// warp-level bf16 MMA (baseline PTX, sm_80+): D += A(16x16) * B(16x8)
__device__ __forceinline__ void mma_bf16(float* c, const uint32_t* a, uint32_t b0, uint32_t b1) {
    asm volatile("mma.sync.aligned.m16n8k16.row.col.f32.bf16.bf16.f32 "
                 "{%0,%1,%2,%3}, {%4,%5,%6,%7}, {%8,%9}, {%0,%1,%2,%3};"
                 : "+f"(c[0]), "+f"(c[1]), "+f"(c[2]), "+f"(c[3])
                 : "r"(a[0]), "r"(a[1]), "r"(a[2]), "r"(a[3]), "r"(b0), "r"(b1));
}
__device__ __forceinline__ void ldsm_x4(uint32_t* r, uint32_t addr) {
    asm volatile("ldmatrix.sync.aligned.m8n8.x4.shared.b16 {%0,%1,%2,%3}, [%4];"
                 : "=r"(r[0]), "=r"(r[1]), "=r"(r[2]), "=r"(r[3]) : "r"(addr));
}

// tiles are 128 rows x 256 bytes; swizzle XORs row low bits into 16B-chunk index
__device__ __forceinline__ void st_row16(char* tile, int row, int chunk, uint4 v) {
    int byte = row * 256 + chunk * 16;
    byte ^= (byte >> 4) & 0x70;
    *(uint4*)(tile + byte) = v;
}
// ldmatrix.x4 source address for one thread: 16x16 bf16 block at (row0, kbyte0)
__device__ __forceinline__ uint32_t frag_addr(uint32_t base, int row0, int kb, int lane) {
    int byte = (row0 + (lane & 15)) * 256 + kb + ((lane >> 4) << 4);
    byte ^= (byte >> 4) & 0x70;
    return base + (uint32_t)byte;
}

// ---------------- preprocessing ----------------
__global__ void k_sniff(const int* ei) {
    __shared__ int ok;
    if (threadIdx.x == 0) ok = 1;
    __syncthreads();
    int hi = ei[2 * threadIdx.x + 1];
    if (hi != 0) atomicExch(&ok, 0);
    __syncthreads();
    if (threadIdx.x == 0) g_is64 = ok;
}

__global__ void k_zero() {
    int i = blockIdx.x * blockDim.x + threadIdx.x;
    if (i < NSEG) g_cnt_seg[i] = 0u;
    if (i < RR)   g_rel_cnt[i] = 0;
}

__global__ void k_decode(const void* ei, const void* et) {
    int e = blockIdx.x * blockDim.x + threadIdx.x;
    if (e >= NE) return;
    if (g_is64) {
        const long long* a = (const long long*)ei;
        const long long* b = (const long long*)et;
        g_srcA[e] = (int)a[e];
        g_dstA[e] = (int)a[NE + e];
        g_relA[e] = (int)b[e];
    } else {
        const int* a = (const int*)ei;
        const int* b = (const int*)et;
        g_srcA[e] = a[e];
        g_dstA[e] = a[NE + e];
        g_relA[e] = b[e];
    }
}

__global__ void k_count() {
    __shared__ int sh[RR];
    int t = threadIdx.x;
    if (t < RR) sh[t] = 0;
    __syncthreads();
    int e = blockIdx.x * blockDim.x + t;
    if (e < NE) {
        int r = g_relA[e], d = g_dstA[e];
        atomicAdd(&g_cnt_seg[d * RR + r], 1u);
        atomicAdd(&sh[r], 1);
    }
    __syncthreads();
    if (t < RR && sh[t]) atomicAdd(&g_rel_cnt[t], sh[t]);
}

__global__ void k_scan() {
    int acc = 0;
    for (int r = 0; r < RR; r++) {
        g_rel_ptr[r] = acc;
        g_rel_cur[r] = acc;
        acc += g_rel_cnt[r];
    }
    g_rel_ptr[RR] = acc;
}

__global__ void k_scatter() {
    int e = blockIdx.x * blockDim.x + threadIdx.x;
    if (e >= NE) return;
    int r = g_relA[e], s = g_srcA[e], d = g_dstA[e];
    int pos = atomicAdd(&g_rel_cur[r], 1);
    g_epack[pos] = (unsigned)s | ((unsigned)d << 16);
    g_einv[pos]  = 1.0f / (float)g_cnt_seg[d * RR + r];
}

__global__ void k_init(const float* __restrict__ b1, const float* __restrict__ b2,
                       float* __restrict__ out) {
    int i = blockIdx.x * blockDim.x + threadIdx.x;
    if (i >= NN * HID) return;
    int h = i & (HID - 1);
    g_h1[i] = b1[h];
    out[i]  = b2[h];
}

// relu + bf16 split of h1
__global__ void k_relu_cvt() {
    int i = blockIdx.x * blockDim.x + threadIdx.x;
    if (i >= NN * HID) return;
    float h = fmaxf(g_h1[i], 0.0f);
    __nv_bfloat16 hi = __float2bfloat16(h);
    __nv_bfloat16 lo = __float2bfloat16(h - __bfloat162float(hi));
    g_h1hi[i] = hi;
    g_h1lo[i] = lo;
}

// transpose + split layer-2 weights: g_w2*[((r*128+n)*128)+k] = split(W[r][k][n])
__global__ void k_wcvt(const float* __restrict__ W2, const float* __restrict__ root2) {
    int idx = blockIdx.x * blockDim.x + threadIdx.x;
    if (idx >= (RR + 1) * HID * HID) return;
    int r = idx >> 14, n = (idx >> 7) & 127, k = idx & 127;
    float w = (r < RR) ? W2[((size_t)r * HID + k) * HID + n] : root2[(size_t)k * HID + n];
    __nv_bfloat16 hi = __float2bfloat16(w);
    __nv_bfloat16 lo = __float2bfloat16(w - __bfloat162float(hi));
    g_w2hi[idx] = hi;
    g_w2lo[idx] = lo;
}

// ---------------- layer 1: scalar weight-stationary (proven) ----------------
template <int F, int EPB>
__global__ void __launch_bounds__(256)
k_layer(const float* __restrict__ Xext, const float* __restrict__ W,
        const float* __restrict__ Wroot) {
    extern __shared__ float sm[];
    float* Ws = sm;
    float* hb = sm + F * HID;

    const float* X   = Xext;
    float*       OUT = g_h1;

    const int tid  = threadIdx.x;
    const int lane = tid & 31;
    const int warp = tid >> 5;
    const int lane4 = lane * 4;

    int bid = blockIdx.x, acc = 0, rel = -1, chunk = 0, cnt = 0;
    #pragma unroll 1
    for (int r = 0; r <= RR; r++) {
        int c  = (r < RR) ? g_rel_cnt[r] : NN;
        int nb = (c + EPB - 1) / EPB;
        if (bid < acc + nb) { rel = r; chunk = bid - acc; cnt = c; break; }
        acc += nb;
    }
    if (rel < 0) return;

    const float* Wp = (rel < RR) ? (W + (size_t)rel * F * HID) : Wroot;
    const int base   = (rel < RR) ? g_rel_ptr[rel] : 0;
    const int cstart = chunk * EPB;

    for (int i = tid * 4; i < F * HID; i += 256 * 4)
        *(float4*)&Ws[i] = *(const float4*)&Wp[i];
    __syncthreads();

    float* hbw = hb + warp * (8 * F);
    const int ngroups = EPB / 8;

    for (int g = warp; g < ngroups; g += 8) {
        int gbase = cstart + g * 8;
        if (gbase >= cnt) break;

        int ms = 0, md = 0; float mi = 0.0f;
        if (lane < 8) {
            int gl = gbase + lane;
            if (gl < cnt) {
                if (rel < RR) {
                    unsigned pk = g_epack[base + gl];
                    ms = (int)(pk & 0xFFFFu);
                    md = (int)(pk >> 16);
                    mi = g_einv[base + gl];
                } else {
                    ms = gl; md = gl; mi = 1.0f;
                }
            }
        }
        int srcs[8], dsts[8]; float invs[8];
        #pragma unroll
        for (int e = 0; e < 8; e++) {
            srcs[e] = __shfl_sync(0xffffffffu, ms, e);
            dsts[e] = __shfl_sync(0xffffffffu, md, e);
            invs[e] = __shfl_sync(0xffffffffu, mi, e);
        }

        __syncwarp();
        if (lane < 16) {
            #pragma unroll
            for (int e = 0; e < 8; e++)
                hbw[e * F + lane] = X[(size_t)srcs[e] * F + lane];
        }
        __syncwarp();

        float a0[8], a1[8], a2[8], a3[8];
        #pragma unroll
        for (int e = 0; e < 8; e++) { a0[e] = a1[e] = a2[e] = a3[e] = 0.0f; }

        #pragma unroll 4
        for (int f = 0; f < F; f++) {
            float4 wv = *(float4*)&Ws[f * HID + lane4];
            #pragma unroll
            for (int e = 0; e < 8; e++) {
                float hv = hbw[e * F + f];
                a0[e] += hv * wv.x;
                a1[e] += hv * wv.y;
                a2[e] += hv * wv.z;
                a3[e] += hv * wv.w;
            }
        }

        #pragma unroll
        for (int e = 0; e < 8; e++) {
            float iv = invs[e];
            if (iv > 0.0f) {
                red_add_v4(OUT + (size_t)dsts[e] * HID + lane4,
                           a0[e] * iv, a1[e] * iv, a2[e] * iv, a3[e] * iv);
            }
        }
        __syncwarp();
    }
}

// ---------------- layer 2: warp-MMA bf16-split GEMM per 128-edge tile ----------------
// SMEM: A_hi 32K | A_lo 32K | W_hi 32K | W_lo 32K | meta
#define S_AHI 0
#define S_ALO 32768
#define S_WHI 65536
#define S_WLO 98304
#define S_SRC 131072
#define S_DST 131584
#define S_INV 132096
#define S_SMEM 132608

__global__ void __launch_bounds__(256, 1)
k_tgemm(float* __restrict__ out) {
    extern __shared__ char smp[];
    const int tid  = threadIdx.x;
    const int wid  = tid >> 5;
    const int lane = tid & 31;

    // map block -> (rel 0..32, tile of 128)
    int bid = blockIdx.x, acc = 0, rel = -1, tile = 0, cnt = 0;
    #pragma unroll 1
    for (int r = 0; r <= RR; r++) {
        int c  = (r < RR) ? g_rel_cnt[r] : NN;
        int nb = (c + 127) >> 7;
        if (bid < acc + nb) { rel = r; tile = bid - acc; cnt = c; break; }
        acc += nb;
    }
    if (rel < 0) return;

    const int base  = (rel < RR) ? g_rel_ptr[rel] : 0;
    const int tbase = tile << 7;

    uint32_t sbase = smem_u32(smp);
    int*   s_src = (int*)(smp + S_SRC);
    int*   s_dst = (int*)(smp + S_DST);
    float* s_inv = (float*)(smp + S_INV);

    // per-row metadata
    if (tid < 128) {
        int s = 0, d = 0; float iv = 0.0f;
        int gl = tbase + tid;
        if (gl < cnt) {
            if (rel < RR) {
                unsigned pk = g_epack[base + gl];
                s = (int)(pk & 0xFFFFu);
                d = (int)(pk >> 16);
                iv = g_einv[base + gl];
            } else {
                s = gl; d = gl; iv = 1.0f;
            }
        }
        s_src[tid] = s; s_dst[tid] = d; s_inv[tid] = iv;
    }
    __syncthreads();

    // stage W (this relation) and gathered A rows, swizzled
    {
        int row = tid >> 1, half = tid & 1;
        const uint4* wh = (const uint4*)&g_w2hi[((size_t)rel * HID + row) * HID];
        const uint4* wl = (const uint4*)&g_w2lo[((size_t)rel * HID + row) * HID];
        int src = s_src[row];
        const uint4* rh = (const uint4*)&g_h1hi[(size_t)src * HID];
        const uint4* rl = (const uint4*)&g_h1lo[(size_t)src * HID];
        #pragma unroll
        for (int j = 0; j < 8; j++) {
            int ch = half * 8 + j;
            st_row16((char*)smp + S_WHI, row, ch, wh[ch]);
            st_row16((char*)smp + S_WLO, row, ch, wl[ch]);
            st_row16((char*)smp + S_AHI, row, ch, rh[ch]);
            st_row16((char*)smp + S_ALO, row, ch, rl[ch]);
        }
    }
    __syncthreads();

    // warp w: rows 16w..16w+15, full N=128. acc[nt][4], nt = 16 n-tiles of 8
    float accm[16][4];
    #pragma unroll
    for (int nt = 0; nt < 16; nt++)
        #pragma unroll
        for (int i = 0; i < 4; i++) accm[nt][i] = 0.0f;

    uint32_t ah[4], al[4], bh[4], bl[4];
    #pragma unroll 1
    for (int kc = 0; kc < 8; kc++) {
        int kb = kc * 32;
        ldsm_x4(ah, frag_addr(sbase + S_AHI, wid * 16, kb, lane));
        ldsm_x4(al, frag_addr(sbase + S_ALO, wid * 16, kb, lane));
        #pragma unroll
        for (int ntp = 0; ntp < 8; ntp++) {
            ldsm_x4(bh, frag_addr(sbase + S_WHI, ntp * 16, kb, lane));
            ldsm_x4(bl, frag_addr(sbase + S_WLO, ntp * 16, kb, lane));
            // even n-tile uses (b0,b2), odd uses (b1,b3)
            mma_bf16(accm[2 * ntp],     ah, bh[0], bh[2]);
            mma_bf16(accm[2 * ntp],     ah, bl[0], bl[2]);
            mma_bf16(accm[2 * ntp],     al, bh[0], bh[2]);
            mma_bf16(accm[2 * ntp + 1], ah, bh[1], bh[3]);
            mma_bf16(accm[2 * ntp + 1], ah, bl[1], bl[3]);
            mma_bf16(accm[2 * ntp + 1], al, bh[1], bh[3]);
        }
    }

    // epilogue: fragment rows g, g+8; cols 2t,2t+1 per n-tile -> scaled RED.v2
    {
        int g = lane >> 2, t = lane & 3;
        int r0 = wid * 16 + g, r1 = r0 + 8;
        float iv0 = s_inv[r0], iv1 = s_inv[r1];
        float* o0 = out + (size_t)s_dst[r0] * HID + t * 2;
        float* o1 = out + (size_t)s_dst[r1] * HID + t * 2;
        #pragma unroll
        for (int nt = 0; nt < 16; nt++) {
            int off = nt * 8;
            if (iv0 > 0.0f) red_add_v2(o0 + off, accm[nt][0] * iv0, accm[nt][1] * iv0);
            if (iv1 > 0.0f) red_add_v2(o1 + off, accm[nt][2] * iv1, accm[nt][3] * iv1);
        }
    }
}

// ---------------- launch ----------------
extern "C" void kernel_launch(void* const* d_in, const int* in_sizes, int n_in,
                              void* d_out, int out_size) {
    const void*  ei = d_in[0];
    const void*  et = d_in[1];
    const float* x  = (const float*)d_in[2];
    const float* W1 = (const float*)d_in[3];
    const float* r1 = (const float*)d_in[4];
    const float* b1 = (const float*)d_in[5];
    const float* W2 = (const float*)d_in[6];
    const float* r2 = (const float*)d_in[7];
    const float* b2 = (const float*)d_in[8];
    float* out = (float*)d_out;

    const int SM1 = (EMBD * HID + 8 * 8 * EMBD) * 4;   // 12 KB

    static bool attr_done = false;
    if (!attr_done) {
        cudaFuncSetAttribute((const void*)k_tgemm,
                             cudaFuncAttributeMaxDynamicSharedMemorySize, S_SMEM);
        attr_done = true;
    }

    k_sniff  <<<1, 256>>>((const int*)ei);
    k_zero   <<<(NSEG + 255) / 256, 256>>>();
    k_decode <<<(NE + 255) / 256, 256>>>(ei, et);
    k_count  <<<(NE + 255) / 256, 256>>>();
    k_scan   <<<1, 1>>>();
    k_scatter<<<(NE + 255) / 256, 256>>>();
    k_init   <<<(NN * HID + 255) / 256, 256>>>(b1, b2, out);
    k_wcvt   <<<((RR + 1) * HID * HID + 255) / 256, 256>>>(W2, r2);

    // layer 1: scalar path, writes g_h1 (pre-initialized with b1)
    k_layer<EMBD, EPB1><<<GRID1, 256, SM1>>>(x, W1, r1);
    k_relu_cvt<<<(NN * HID + 255) / 256, 256>>>();
    // layer 2: tensor path (warp MMA), REDs into out (pre-initialized with b2)
    k_tgemm  <<<GRID_T, 256, S_SMEM>>>(out);
}